// round 8
// baseline (speedup 1.0000x reference)
#include <cuda_runtime.h>
#include <cstdint>

#define NE    16
#define NTOK  4096
#define INF   1024
#define OUTF  2048
#define BM    128
#define BN    128
#define BK    32
#define NKI   (INF / BK)          // 32 k-chunks
#define MAXMT (NTOK / BM + NE)    // 48 worst-case m-tiles
#define LDA   36                  // smem row stride in floats (32 + 4 pad)

// ---- device scratch ----
__device__ int g_off[NE + 1];
__device__ int g_sorted[NTOK];
__device__ int g_tile[NE + 1];

// ---- fused routing: hist + scan + scatter in one block ----
__global__ __launch_bounds__(1024) void k_route(const int* __restrict__ gate) {
    __shared__ int sc[NE];
    __shared__ int sfill[NE];
    const int tid = threadIdx.x;
    if (tid < NE) sc[tid] = 0;
    __syncthreads();
    for (int t = tid; t < NTOK; t += 1024) atomicAdd(&sc[gate[t]], 1);
    __syncthreads();
    if (tid == 0) {
        int s = 0, ts = 0;
        for (int e = 0; e < NE; e++) {
            g_off[e] = s; sfill[e] = s; g_tile[e] = ts;
            int c = sc[e];
            s += c; ts += (c + BM - 1) / BM;
        }
        g_off[NE] = s; g_tile[NE] = ts;
    }
    __syncthreads();
    for (int t = tid; t < NTOK; t += 1024) {
        int p = atomicAdd(&sfill[gate[t]], 1);
        g_sorted[p] = t;
    }
}

// ---- helpers ----
__device__ __forceinline__ uint32_t smem_u32(const void* p) {
    uint32_t a;
    asm("{ .reg .u64 t; cvta.to.shared.u64 t, %1; cvt.u32.u64 %0, t; }" : "=r"(a) : "l"(p));
    return a;
}
// .cg: bypass L1 allocation (tiles are consumed from smem, never re-read via L1)
__device__ __forceinline__ void cp16(uint32_t dst, const void* src, uint32_t srcsz) {
    asm volatile("cp.async.cg.shared.global [%0], [%1], 16, %2;"
                 :: "r"(dst), "l"(src), "r"(srcsz) : "memory");
}
#define CP_COMMIT() asm volatile("cp.async.commit_group;" ::: "memory")
#define CP_WAIT(n)  asm volatile("cp.async.wait_group %0;" :: "n"(n) : "memory")

__device__ __forceinline__ void mma_tf32(float c[4], const uint32_t a[4],
                                         uint32_t b0, uint32_t b1) {
    asm volatile(
        "mma.sync.aligned.m16n8k8.row.col.f32.tf32.tf32.f32 "
        "{%0,%1,%2,%3}, {%4,%5,%6,%7}, {%8,%9}, {%0,%1,%2,%3};"
        : "+f"(c[0]), "+f"(c[1]), "+f"(c[2]), "+f"(c[3])
        : "r"(a[0]), "r"(a[1]), "r"(a[2]), "r"(a[3]), "r"(b0), "r"(b1));
}
__device__ __forceinline__ void ldsm_x4(uint32_t r[4], uint32_t addr) {
    asm volatile("ldmatrix.sync.aligned.m8n8.x4.shared.b16 {%0,%1,%2,%3}, [%4];"
                 : "=r"(r[0]), "=r"(r[1]), "=r"(r[2]), "=r"(r[3]) : "r"(addr));
}

// SMEM (floats): A at buf*9216, B at 4608 + buf*9216; rowTok after
#define SM_FLOATS  18432
#define SMEM_BYTES (SM_FLOATS * 4 + 512)
#define BUF_BYTES  (9216 * 4)

// ---- grouped GEMM: out[tok, n] = x[tok,:] . W[e, n, :] (tf32 mma, fp32 acc) ----
__global__ __launch_bounds__(256, 2) void k_gemm(
    const float* __restrict__ x,
    const float* __restrict__ w,
    float* __restrict__ out)
{
    const int mt = blockIdx.x;
    if (mt >= g_tile[NE]) return;
    const int n0 = blockIdx.y * BN;

    extern __shared__ float smf[];
    int* rowTok = (int*)(smf + SM_FLOATS);

    const int tid = threadIdx.x;
    const int wid = tid >> 5;
    const int ln  = tid & 31;

    int e = 0;
#pragma unroll
    for (int i = 1; i < NE; i++) e += (mt >= g_tile[i]);
    const int seg_start = g_off[e];
    const int seg_cnt   = g_off[e + 1] - seg_start;
    const int m0        = (mt - g_tile[e]) * BM;

    if (tid < BM) {
        int idx = m0 + tid;
        rowTok[tid] = (idx < seg_cnt) ? g_sorted[seg_start + idx] : -1;
    }
    __syncthreads();

    // ---- loader: thread -> rows (tid>>3)+32i, 16B unit (tid&7) ----
    const int lr = tid >> 3;
    const int lq = tid & 7;
    const float* wbase = w + (size_t)e * OUTF * INF;
    int ltok[4];
    const float* asrc[4];
    const float* bsrc[4];
#pragma unroll
    for (int i = 0; i < 4; i++) {
        int r = lr + 32 * i;
        ltok[i] = rowTok[r];
        asrc[i] = x + (size_t)((ltok[i] < 0) ? 0 : ltok[i]) * INF + lq * 4;
        bsrc[i] = wbase + (size_t)(n0 + r) * INF + lq * 4;
    }
    const uint32_t sbase = smem_u32(smf);
    uint32_t adst[4], bdst[4];
#pragma unroll
    for (int i = 0; i < 4; i++) {
        adst[i] = sbase + ((lr + 32 * i) * LDA + lq * 4) * 4;
        bdst[i] = sbase + (4608 + (lr + 32 * i) * LDA + lq * 4) * 4;
    }

    // ---- compute setup: warp (wm, wn) owns 64m x 32n ----
    const int wm = wid >> 2;
    const int wn = wid & 3;
    // A ldmatrix x4: matrices (r,k),(r+8,k),(r,k+4),(r+8,k+4)
    const int amat = ln >> 3;          // 0..3
    const int arow = wm * 64 + ((amat & 1) << 3) + (ln & 7);
    const uint32_t aOff0 = (uint32_t)((arow * LDA + (amat >> 1) * 4) * 4);
    // B ldmatrix x4 covering n16 x k8: groups g=ln>>3 ->
    //   row = wn*32 + (g>>1)*8 + (ln&7), col = (g&1)*4 floats
    {
    }
    const int bg = ln >> 3;
    const int brow = wn * 32 + ((bg >> 1) << 3) + (ln & 7);
    const uint32_t bOff0 = (uint32_t)(((4608 + brow * LDA) + (bg & 1) * 4) * 4);

    float c[4][4][4];
#pragma unroll
    for (int i = 0; i < 4; i++)
#pragma unroll
        for (int j = 0; j < 4; j++) {
            c[i][j][0] = 0.f; c[i][j][1] = 0.f; c[i][j][2] = 0.f; c[i][j][3] = 0.f;
        }

    // prologue: chunk 0 -> buffer 0
#pragma unroll
    for (int i = 0; i < 4; i++) {
        cp16(adst[i], asrc[i], ltok[i] < 0 ? 0u : 16u);
        cp16(bdst[i], bsrc[i], 16u);
    }
    CP_COMMIT();

    for (int it = 0; it < NKI; it++) {
        const int cbuf = it & 1;
        if (it + 1 < NKI) {
            const uint32_t nbo = (uint32_t)(((it + 1) & 1) * BUF_BYTES);
            const int koff = (it + 1) * BK;
#pragma unroll
            for (int i = 0; i < 4; i++) {
                cp16(adst[i] + nbo, asrc[i] + koff, ltok[i] < 0 ? 0u : 16u);
                cp16(bdst[i] + nbo, bsrc[i] + koff, 16u);
            }
            CP_COMMIT();
            CP_WAIT(1);
        } else {
            CP_WAIT(0);
        }
        __syncthreads();

        const uint32_t aB = sbase + cbuf * BUF_BYTES + aOff0;
        const uint32_t bB = sbase + cbuf * BUF_BYTES + bOff0;

#pragma unroll
        for (int ks = 0; ks < 4; ks++) {
            uint32_t a[4][4], b[2][4];
#pragma unroll
            for (int mtl = 0; mtl < 4; mtl++)
                ldsm_x4(a[mtl], aB + (mtl * 16 * LDA + ks * 8) * 4);
#pragma unroll
            for (int np = 0; np < 2; np++)   // n16 x k8 per x4 (two n-tiles)
                ldsm_x4(b[np], bB + (np * 16 * LDA + ks * 8) * 4);
#pragma unroll
            for (int mtl = 0; mtl < 4; mtl++)
#pragma unroll
                for (int nt = 0; nt < 4; nt++)
                    mma_tf32(c[mtl][nt], a[mtl],
                             b[nt >> 1][(nt & 1) * 2], b[nt >> 1][(nt & 1) * 2 + 1]);
        }
        __syncthreads();
    }

    // ---- epilogue: scatter rows to original tokens ----
    const int colBase = n0 + wn * 32 + 2 * (ln & 3);
#pragma unroll
    for (int mtl = 0; mtl < 4; mtl++) {
        int r0 = wm * 64 + mtl * 16 + (ln >> 2);
        int tok0 = rowTok[r0];
        int tok1 = rowTok[r0 + 8];
        if (tok0 >= 0) {
            float* po = out + (size_t)tok0 * OUTF + colBase;
#pragma unroll
            for (int nt = 0; nt < 4; nt++)
                *(float2*)(po + nt * 8) = make_float2(c[mtl][nt][0], c[mtl][nt][1]);
        }
        if (tok1 >= 0) {
            float* po = out + (size_t)tok1 * OUTF + colBase;
#pragma unroll
            for (int nt = 0; nt < 4; nt++)
                *(float2*)(po + nt * 8) = make_float2(c[mtl][nt][2], c[mtl][nt][3]);
        }
    }
}

extern "C" void kernel_launch(void* const* d_in, const int* in_sizes, int n_in,
                              void* d_out, int out_size)
{
    const float* x    = (const float*)d_in[0];
    const int*   gate = (const int*)d_in[1];
    const float* w    = (const float*)d_in[2];
    float*       out  = (float*)d_out;

    cudaFuncSetAttribute(k_gemm, cudaFuncAttributeMaxDynamicSharedMemorySize, SMEM_BYTES);

    k_route<<<1, 1024>>>(gate);

    dim3 grid(MAXMT, OUTF / BN);   // 48 x 16
    k_gemm<<<grid, 256, SMEM_BYTES>>>(x, w, out);
}